// round 2
// baseline (speedup 1.0000x reference)
#include <cuda_runtime.h>

#define B_ 4
#define N_ 128
#define L_ 20
#define D_ 512
#define KR (B_*L_)            // 80
#define SCALE 0.044194173824159216f   // 1/sqrt(512)

// ---- scratch (no allocation allowed) ----
__device__ float g_k[KR*D_];          // k = f_w @ Wk^T + bk
__device__ float g_kk[KR*D_];         // kk = k @ Wq
__device__ float g_c[KR];             // c  = bq . k
__device__ float g_fbq[B_*N_*D_];     // gated boundary features
__device__ float g_Ab[B_*N_*N_];      // boundary self-attention
__device__ float g_part[B_*4*N_*N_];  // K-split GEMM partials (also holds 4*80*512)

// ============================================================
// Generic fp32 K-split partial GEMM.
// TRANSB:  C[r][c] = sum_k A[r][k]*B[c][k]
// !TRANSB: C[r][c] = sum_k A[r][k]*B[k][c]
// Tile 16x128, 128 threads, 4x4 micro-tile, KC=16.
// Cpart layout: [(batch*nsplit+split)][M][Ncol]
// ============================================================
template<bool TRANSB>
__global__ void __launch_bounds__(128)
gemm_part(const float* __restrict__ A, const float* __restrict__ B,
          float* __restrict__ Cpart, int M, int Ncol, int K, int ldB,
          int nsplit, int strideA, int strideB)
{
    const int TM = 16, TN = 128, KC = 16;
    int batch = blockIdx.z / nsplit;
    int split = blockIdx.z - batch * nsplit;
    int klen  = K / nsplit;
    int kbase = split * klen;
    A += (long)batch * strideA;
    B += (long)batch * strideB;
    float* C = Cpart + (long)(batch * nsplit + split) * M * Ncol;

    __shared__ float As[KC][TM];
    __shared__ float Bs[KC][TN];

    int row0 = blockIdx.x * TM;
    int col0 = blockIdx.y * TN;
    int tid = threadIdx.x;
    int tr = tid >> 5;      // 0..3
    int tc = tid & 31;      // 0..31

    float acc[4][4];
    #pragma unroll
    for (int i = 0; i < 4; i++)
        #pragma unroll
        for (int j = 0; j < 4; j++) acc[i][j] = 0.f;

    for (int kb = 0; kb < klen; kb += KC) {
        int k0 = kbase + kb;
        // A tile: 16 rows x 16 k
        {
            int idx = tid * 2;
            int r = idx >> 4, kc = idx & 15;
            float2 av = *(const float2*)(A + (long)(row0 + r) * K + k0 + kc);
            As[kc][r]     = av.x;
            As[kc + 1][r] = av.y;
        }
        // B tile: 16 k x 128 cols
        if (TRANSB) {
            const float* bp = B + (long)(col0 + tid) * ldB + k0;
            #pragma unroll
            for (int q = 0; q < 4; q++) {
                float4 v = *(const float4*)(bp + q * 4);
                Bs[q*4+0][tid] = v.x; Bs[q*4+1][tid] = v.y;
                Bs[q*4+2][tid] = v.z; Bs[q*4+3][tid] = v.w;
            }
        } else {
            #pragma unroll
            for (int p = 0; p < 4; p++) {
                int kc = (tid >> 5) + p * 4;
                int c4 = (tid & 31) * 4;
                float4 v = *(const float4*)(B + (long)(k0 + kc) * ldB + col0 + c4);
                *(float4*)&Bs[kc][c4] = v;
            }
        }
        __syncthreads();
        #pragma unroll
        for (int kc = 0; kc < KC; kc++) {
            float4 a4 = ((const float4*)As[kc])[tr];
            float4 b4 = ((const float4*)Bs[kc])[tc];
            acc[0][0] += a4.x*b4.x; acc[0][1] += a4.x*b4.y; acc[0][2] += a4.x*b4.z; acc[0][3] += a4.x*b4.w;
            acc[1][0] += a4.y*b4.x; acc[1][1] += a4.y*b4.y; acc[1][2] += a4.y*b4.z; acc[1][3] += a4.y*b4.w;
            acc[2][0] += a4.z*b4.x; acc[2][1] += a4.z*b4.y; acc[2][2] += a4.z*b4.z; acc[2][3] += a4.z*b4.w;
            acc[3][0] += a4.w*b4.x; acc[3][1] += a4.w*b4.y; acc[3][2] += a4.w*b4.z; acc[3][3] += a4.w*b4.w;
        }
        __syncthreads();
    }
    #pragma unroll
    for (int i = 0; i < 4; i++) {
        int row = row0 + tr * 4 + i;
        float4 v = make_float4(acc[i][0], acc[i][1], acc[i][2], acc[i][3]);
        *(float4*)(C + (long)row * Ncol + col0 + tc * 4) = v;
    }
}

// k = sum(partials) + bk ; c[r] = bq . k[r]
__global__ void __launch_bounds__(512) reduce_k_bias(const float* __restrict__ bk,
                                                     const float* __restrict__ bq)
{
    int r = blockIdx.x, d = threadIdx.x;
    float v = g_part[r*D_ + d] + g_part[(KR + r)*D_ + d]
            + g_part[(2*KR + r)*D_ + d] + g_part[(3*KR + r)*D_ + d] + bk[d];
    g_k[r*D_ + d] = v;
    float p = v * bq[d];
    #pragma unroll
    for (int off = 16; off > 0; off >>= 1) p += __shfl_xor_sync(0xffffffffu, p, off);
    __shared__ float red[16];
    if ((d & 31) == 0) red[d >> 5] = p;
    __syncthreads();
    if (d < 32) {
        float s = (d < 16) ? red[d] : 0.f;
        #pragma unroll
        for (int off = 8; off > 0; off >>= 1) s += __shfl_xor_sync(0xffffffffu, s, off);
        if (d == 0) g_c[r] = s;
    }
}

__global__ void __launch_bounds__(256) reduce_kk()
{
    int i = blockIdx.x * blockDim.x + threadIdx.x;   // < 80*512
    g_kk[i] = g_part[i] + g_part[KR*D_ + i] + g_part[2*KR*D_ + i] + g_part[3*KR*D_ + i];
}

// cross-attention (L=20) + sentence gating -> f_bq
__global__ void __launch_bounds__(256) attn_kernel(const float* __restrict__ f_b,
                                                   const float* __restrict__ f_w,
                                                   const float* __restrict__ f_s)
{
    int bn = blockIdx.x; int b = bn >> 7;
    __shared__ float fb[D_];
    __shared__ float sl[L_];
    int tid = threadIdx.x;
    fb[tid]       = f_b[bn*D_ + tid];
    fb[tid + 256] = f_b[bn*D_ + tid + 256];
    __syncthreads();
    int w = tid >> 5, lane = tid & 31;
    for (int l = w; l < L_; l += 8) {
        const float* kr = g_kk + (b*L_ + l) * D_;
        float p = 0.f;
        #pragma unroll
        for (int e = lane; e < D_; e += 32) p += fb[e] * kr[e];
        #pragma unroll
        for (int off = 16; off > 0; off >>= 1) p += __shfl_xor_sync(0xffffffffu, p, off);
        if (lane == 0) sl[l] = (p + g_c[b*L_ + l]) * SCALE;
    }
    __syncthreads();
    if (tid == 0) {
        float mx = sl[0];
        #pragma unroll
        for (int l = 1; l < L_; l++) mx = fmaxf(mx, sl[l]);
        float s = 0.f;
        #pragma unroll
        for (int l = 0; l < L_; l++) { float e = __expf(sl[l] - mx); sl[l] = e; s += e; }
        float inv = __fdividef(1.f, s);
        #pragma unroll
        for (int l = 0; l < L_; l++) sl[l] *= inv;
    }
    __syncthreads();
    for (int d = tid; d < D_; d += 256) {
        float acc = 0.f;
        #pragma unroll
        for (int l = 0; l < L_; l++) acc += sl[l] * f_w[(b*L_ + l)*D_ + d];
        g_fbq[bn*D_ + d] = fb[d] * (acc + f_s[b*D_ + d]);
    }
}

// sum score partials, scale, row softmax -> A_b
__global__ void __launch_bounds__(128) score_softmax()
{
    int bn = blockIdx.x; int b = bn >> 7; int n = bn & 127;
    int m = threadIdx.x;
    float s = 0.f;
    #pragma unroll
    for (int sp = 0; sp < 4; sp++) s += g_part[(((b*4 + sp)*N_) + n)*N_ + m];
    s *= SCALE;
    __shared__ float red[4];
    float mx = s;
    #pragma unroll
    for (int off = 16; off > 0; off >>= 1) mx = fmaxf(mx, __shfl_xor_sync(0xffffffffu, mx, off));
    if ((m & 31) == 0) red[m >> 5] = mx;
    __syncthreads();
    mx = fmaxf(fmaxf(red[0], red[1]), fmaxf(red[2], red[3]));
    float e = __expf(s - mx);
    __syncthreads();
    float sm = e;
    #pragma unroll
    for (int off = 16; off > 0; off >>= 1) sm += __shfl_xor_sync(0xffffffffu, sm, off);
    if ((m & 31) == 0) red[m >> 5] = sm;
    __syncthreads();
    sm = red[0] + red[1] + red[2] + red[3];
    g_Ab[bn*N_ + m] = e * __fdividef(1.f, sm);
}

// f_bb + f_b + f_bm : the DRAM-bound f_m streaming kernel.
// block = (b, 4 consecutive j); thread = d; loop over m.
__global__ void __launch_bounds__(512) final_kernel(const float* __restrict__ f_b,
                                                    const float* __restrict__ f_s,
                                                    const float* __restrict__ f_m,
                                                    float* __restrict__ out)
{
    int bidx = blockIdx.x;          // 0..127
    int b  = bidx >> 5;
    int j0 = (bidx & 31) * 4;
    int d  = threadIdx.x;

    __shared__ float2 a2[4][N_];    // {A_b[b][j][m], A_b[b][m][j]}
    {
        int jj = d >> 7, m = d & 127;   // 512 threads cover 4x128 exactly
        float row = g_Ab[(b*N_ + j0 + jj)*N_ + m];
        float col = g_Ab[(b*N_ + m)*N_ + j0 + jj];
        a2[jj][m] = make_float2(row, col);
    }
    __syncthreads();

    float fsd = f_s[b*D_ + d];
    float accbb[4] = {0.f, 0.f, 0.f, 0.f};
    float accbm[4] = {0.f, 0.f, 0.f, 0.f};
    const float* fmp = f_m + ((b*N_)*N_ + j0)*D_ + d;
    const float* fbp = f_b + (b*N_)*D_ + d;

    #pragma unroll 2
    for (int m = 0; m < N_; m++) {
        float fbv = fbp[m*D_];
        #pragma unroll
        for (int jj = 0; jj < 4; jj++) {
            float x = fmp[m*(N_*D_) + jj*D_];
            float2 a = a2[jj][m];
            accbb[jj] = fmaf(a.x, fbv, accbb[jj]);
            float sg = __fdividef(1.f, 1.f + __expf(-x * fsd));
            accbm[jj] = fmaf(a.y * sg, x, accbm[jj]);
        }
    }
    #pragma unroll
    for (int jj = 0; jj < 4; jj++)
        out[(b*N_ + j0 + jj)*D_ + d] =
            accbb[jj] + f_b[(b*N_ + j0 + jj)*D_ + d] + accbm[jj];
}

extern "C" void kernel_launch(void* const* d_in, const int* in_sizes, int n_in,
                              void* d_out, int out_size)
{
    const float* f_b = (const float*)d_in[0];
    const float* f_w = (const float*)d_in[1];
    const float* f_s = (const float*)d_in[2];
    const float* f_m = (const float*)d_in[3];
    const float* Wq  = (const float*)d_in[4];
    const float* bq  = (const float*)d_in[5];
    const float* Wk  = (const float*)d_in[6];
    const float* bk  = (const float*)d_in[7];
    float* out = (float*)d_out;

    void *p_part, *p_k, *p_fbq;
    cudaGetSymbolAddress(&p_part, g_part);
    cudaGetSymbolAddress(&p_k,    g_k);
    cudaGetSymbolAddress(&p_fbq,  g_fbq);

    // 1) k partials: f_w[80,512] @ Wk^T        (NT, K-split 4)
    gemm_part<true><<<dim3(5, 4, 4), 128>>>(f_w, Wk, (float*)p_part,
                                            KR, D_, D_, D_, 4, 0, 0);
    // 2) k = sum + bk ; c = bq . k
    reduce_k_bias<<<KR, 512>>>(bk, bq);
    // 3) kk partials: k @ Wq                   (NN, K-split 4)
    gemm_part<false><<<dim3(5, 4, 4), 128>>>((const float*)p_k, Wq, (float*)p_part,
                                             KR, D_, D_, D_, 4, 0, 0);
    reduce_kk<<<160, 256>>>();
    // 4) cross-attn softmax + gating -> f_bq
    attn_kernel<<<B_*N_, 256>>>(f_b, f_w, f_s);
    // 5) self-attn score partials per batch    (NT, batched, K-split 4)
    gemm_part<true><<<dim3(8, 1, 16), 128>>>((const float*)p_fbq, (const float*)p_fbq,
                                             (float*)p_part, N_, N_, D_, D_, 4,
                                             N_*D_, N_*D_);
    score_softmax<<<B_*N_, 128>>>();
    // 6) DRAM-bound f_m stream + both einsum reductions + residual
    final_kernel<<<128, 512>>>(f_b, f_s, f_m, out);
}

// round 3
// speedup vs baseline: 1.6926x; 1.6926x over previous
#include <cuda_runtime.h>

#define B_ 4
#define N_ 128
#define L_ 20
#define D_ 512
#define KR (B_*L_)            // 80
#define SCALE 0.044194173824159216f   // 1/sqrt(512)

// ---- scratch (no allocation allowed) ----
__device__ float g_k[KR*D_];          // k = f_w @ Wk^T + bk
__device__ float g_kk[KR*D_];         // kk = k @ Wq
__device__ float g_c[KR];             // c  = bq . k
__device__ float g_fbq[B_*N_*D_];     // gated boundary features
__device__ float g_Ab[B_*N_*N_];      // boundary self-attention
__device__ float g_part[B_*4*N_*N_];  // K-split GEMM partials (also holds 4*80*512)
__device__ float g_fp[4*B_*N_*D_];    // m-split partials of the final kernel

// ============================================================
// Generic fp32 K-split partial GEMM (unchanged from R1).
// ============================================================
template<bool TRANSB>
__global__ void __launch_bounds__(128)
gemm_part(const float* __restrict__ A, const float* __restrict__ B,
          float* __restrict__ Cpart, int M, int Ncol, int K, int ldB,
          int nsplit, int strideA, int strideB)
{
    const int TM = 16, TN = 128, KC = 16;
    int batch = blockIdx.z / nsplit;
    int split = blockIdx.z - batch * nsplit;
    int klen  = K / nsplit;
    int kbase = split * klen;
    A += (long)batch * strideA;
    B += (long)batch * strideB;
    float* C = Cpart + (long)(batch * nsplit + split) * M * Ncol;

    __shared__ float As[KC][TM];
    __shared__ float Bs[KC][TN];

    int row0 = blockIdx.x * TM;
    int col0 = blockIdx.y * TN;
    int tid = threadIdx.x;
    int tr = tid >> 5;      // 0..3
    int tc = tid & 31;      // 0..31

    float acc[4][4];
    #pragma unroll
    for (int i = 0; i < 4; i++)
        #pragma unroll
        for (int j = 0; j < 4; j++) acc[i][j] = 0.f;

    for (int kb = 0; kb < klen; kb += KC) {
        int k0 = kbase + kb;
        {
            int idx = tid * 2;
            int r = idx >> 4, kc = idx & 15;
            float2 av = *(const float2*)(A + (long)(row0 + r) * K + k0 + kc);
            As[kc][r]     = av.x;
            As[kc + 1][r] = av.y;
        }
        if (TRANSB) {
            const float* bp = B + (long)(col0 + tid) * ldB + k0;
            #pragma unroll
            for (int q = 0; q < 4; q++) {
                float4 v = *(const float4*)(bp + q * 4);
                Bs[q*4+0][tid] = v.x; Bs[q*4+1][tid] = v.y;
                Bs[q*4+2][tid] = v.z; Bs[q*4+3][tid] = v.w;
            }
        } else {
            #pragma unroll
            for (int p = 0; p < 4; p++) {
                int kc = (tid >> 5) + p * 4;
                int c4 = (tid & 31) * 4;
                float4 v = *(const float4*)(B + (long)(k0 + kc) * ldB + col0 + c4);
                *(float4*)&Bs[kc][c4] = v;
            }
        }
        __syncthreads();
        #pragma unroll
        for (int kc = 0; kc < KC; kc++) {
            float4 a4 = ((const float4*)As[kc])[tr];
            float4 b4 = ((const float4*)Bs[kc])[tc];
            acc[0][0] += a4.x*b4.x; acc[0][1] += a4.x*b4.y; acc[0][2] += a4.x*b4.z; acc[0][3] += a4.x*b4.w;
            acc[1][0] += a4.y*b4.x; acc[1][1] += a4.y*b4.y; acc[1][2] += a4.y*b4.z; acc[1][3] += a4.y*b4.w;
            acc[2][0] += a4.z*b4.x; acc[2][1] += a4.z*b4.y; acc[2][2] += a4.z*b4.z; acc[2][3] += a4.z*b4.w;
            acc[3][0] += a4.w*b4.x; acc[3][1] += a4.w*b4.y; acc[3][2] += a4.w*b4.z; acc[3][3] += a4.w*b4.w;
        }
        __syncthreads();
    }
    #pragma unroll
    for (int i = 0; i < 4; i++) {
        int row = row0 + tr * 4 + i;
        float4 v = make_float4(acc[i][0], acc[i][1], acc[i][2], acc[i][3]);
        *(float4*)(C + (long)row * Ncol + col0 + tc * 4) = v;
    }
}

// k = sum(partials) + bk ; c[r] = bq . k[r]
__global__ void __launch_bounds__(512) reduce_k_bias(const float* __restrict__ bk,
                                                     const float* __restrict__ bq)
{
    int r = blockIdx.x, d = threadIdx.x;
    float v = g_part[r*D_ + d] + g_part[(KR + r)*D_ + d]
            + g_part[(2*KR + r)*D_ + d] + g_part[(3*KR + r)*D_ + d] + bk[d];
    g_k[r*D_ + d] = v;
    float p = v * bq[d];
    #pragma unroll
    for (int off = 16; off > 0; off >>= 1) p += __shfl_xor_sync(0xffffffffu, p, off);
    __shared__ float red[16];
    if ((d & 31) == 0) red[d >> 5] = p;
    __syncthreads();
    if (d < 32) {
        float s = (d < 16) ? red[d] : 0.f;
        #pragma unroll
        for (int off = 8; off > 0; off >>= 1) s += __shfl_xor_sync(0xffffffffu, s, off);
        if (d == 0) g_c[r] = s;
    }
}

__global__ void __launch_bounds__(256) reduce_kk()
{
    int i = blockIdx.x * 256 + threadIdx.x;   // over KR*D_/4 = 10240 float4
    const float4* p = (const float4*)g_part;
    float4 a = p[i], b = p[10240 + i], c = p[2*10240 + i], e = p[3*10240 + i];
    ((float4*)g_kk)[i] = make_float4(a.x+b.x+c.x+e.x, a.y+b.y+c.y+e.y,
                                     a.z+b.z+c.z+e.z, a.w+b.w+c.w+e.w);
}

// cross-attention (L=20) + sentence gating -> f_bq
__global__ void __launch_bounds__(256) attn_kernel(const float* __restrict__ f_b,
                                                   const float* __restrict__ f_w,
                                                   const float* __restrict__ f_s)
{
    int bn = blockIdx.x; int b = bn >> 7;
    __shared__ float fb[D_];
    __shared__ float sl[L_];
    int tid = threadIdx.x;
    fb[tid]       = f_b[bn*D_ + tid];
    fb[tid + 256] = f_b[bn*D_ + tid + 256];
    __syncthreads();
    int w = tid >> 5, lane = tid & 31;
    for (int l = w; l < L_; l += 8) {
        const float* kr = g_kk + (b*L_ + l) * D_;
        float p = 0.f;
        #pragma unroll
        for (int e = lane; e < D_; e += 32) p += fb[e] * kr[e];
        #pragma unroll
        for (int off = 16; off > 0; off >>= 1) p += __shfl_xor_sync(0xffffffffu, p, off);
        if (lane == 0) sl[l] = (p + g_c[b*L_ + l]) * SCALE;
    }
    __syncthreads();
    if (tid == 0) {
        float mx = sl[0];
        #pragma unroll
        for (int l = 1; l < L_; l++) mx = fmaxf(mx, sl[l]);
        float s = 0.f;
        #pragma unroll
        for (int l = 0; l < L_; l++) { float e = __expf(sl[l] - mx); sl[l] = e; s += e; }
        float inv = __fdividef(1.f, s);
        #pragma unroll
        for (int l = 0; l < L_; l++) sl[l] *= inv;
    }
    __syncthreads();
    for (int d = tid; d < D_; d += 256) {
        float acc = 0.f;
        #pragma unroll
        for (int l = 0; l < L_; l++) acc += sl[l] * f_w[(b*L_ + l)*D_ + d];
        g_fbq[bn*D_ + d] = fb[d] * (acc + f_s[b*D_ + d]);
    }
}

// sum score partials, scale, row softmax -> A_b
__global__ void __launch_bounds__(128) score_softmax()
{
    int bn = blockIdx.x; int b = bn >> 7; int n = bn & 127;
    int m = threadIdx.x;
    float s = 0.f;
    #pragma unroll
    for (int sp = 0; sp < 4; sp++) s += g_part[(((b*4 + sp)*N_) + n)*N_ + m];
    s *= SCALE;
    __shared__ float red[4];
    float mx = s;
    #pragma unroll
    for (int off = 16; off > 0; off >>= 1) mx = fmaxf(mx, __shfl_xor_sync(0xffffffffu, mx, off));
    if ((m & 31) == 0) red[m >> 5] = mx;
    __syncthreads();
    mx = fmaxf(fmaxf(red[0], red[1]), fmaxf(red[2], red[3]));
    float e = __expf(s - mx);
    __syncthreads();
    float sm = e;
    #pragma unroll
    for (int off = 16; off > 0; off >>= 1) sm += __shfl_xor_sync(0xffffffffu, sm, off);
    if ((m & 31) == 0) red[m >> 5] = sm;
    __syncthreads();
    sm = red[0] + red[1] + red[2] + red[3];
    g_Ab[bn*N_ + m] = e * __fdividef(1.f, sm);
}

// sigmoid(x) = 0.5*tanh(0.5x)+0.5 — 1 MUFU (tanh.approx on sm_75+) instead of 2
__device__ __forceinline__ float sigmoid_fast(float x)
{
    float t;
    asm("tanh.approx.f32 %0, %1;" : "=f"(t) : "f"(0.5f * x));
    return fmaf(0.5f, t, 0.5f);
}

// f_m streaming kernel, m-split x4 for full-chip occupancy & MLP.
// block = (b, 4 consecutive j, 1 of 4 m-chunks); thread = d; loop 32 m's.
// Writes combined (f_bb + f_bm) partial into g_fp[split].
__global__ void __launch_bounds__(512) final_split(const float* __restrict__ f_b,
                                                   const float* __restrict__ f_s,
                                                   const float* __restrict__ f_m)
{
    int bidx  = blockIdx.x;          // 0..511
    int split = bidx & 3;
    int jg    = (bidx >> 2) & 31;
    int b     = bidx >> 7;
    int j0    = jg * 4;
    int m0    = split * 32;
    int d     = threadIdx.x;

    __shared__ float2 a2[4][32];     // {A_b[b][j][m], A_b[b][m][j]} for this m-chunk
    if (d < 128) {
        int jj = d >> 5, m = d & 31;
        a2[jj][m] = make_float2(g_Ab[(b*N_ + j0 + jj)*N_ + m0 + m],
                                g_Ab[(b*N_ + m0 + m)*N_ + j0 + jj]);
    }
    __syncthreads();

    float fsd = f_s[b*D_ + d];
    float acc[4] = {0.f, 0.f, 0.f, 0.f};
    const float* fmp = f_m + (((long)(b*N_ + m0))*N_ + j0)*D_ + d;
    const float* fbp = f_b + (b*N_ + m0)*D_ + d;

    #pragma unroll 4
    for (int m = 0; m < 32; m++) {
        float fbv = fbp[m*D_];
        #pragma unroll
        for (int jj = 0; jj < 4; jj++) {
            float x = fmp[(long)m*(N_*D_) + jj*D_];
            float2 a = a2[jj][m];
            float sg = sigmoid_fast(x * fsd);
            acc[jj] = fmaf(a.x, fbv, acc[jj]);
            acc[jj] = fmaf(a.y * sg, x, acc[jj]);
        }
    }
    #pragma unroll
    for (int jj = 0; jj < 4; jj++)
        g_fp[((split*B_ + b)*N_ + j0 + jj)*D_ + d] = acc[jj];
}

// out = f_b + sum of 4 m-split partials (float4, 64K vectors)
__global__ void __launch_bounds__(512) reduce_final(const float* __restrict__ f_b,
                                                    float* __restrict__ out)
{
    int i = blockIdx.x * 512 + threadIdx.x;   // over B*N*D/4 = 65536 float4
    const int S = B_*N_*D_/4;                  // 65536
    const float4* p = (const float4*)g_fp;
    float4 r = ((const float4*)f_b)[i];
    float4 a = p[i], bb = p[S + i], c = p[2*S + i], e = p[3*S + i];
    r.x += a.x + bb.x + c.x + e.x;
    r.y += a.y + bb.y + c.y + e.y;
    r.z += a.z + bb.z + c.z + e.z;
    r.w += a.w + bb.w + c.w + e.w;
    ((float4*)out)[i] = r;
}

extern "C" void kernel_launch(void* const* d_in, const int* in_sizes, int n_in,
                              void* d_out, int out_size)
{
    const float* f_b = (const float*)d_in[0];
    const float* f_w = (const float*)d_in[1];
    const float* f_s = (const float*)d_in[2];
    const float* f_m = (const float*)d_in[3];
    const float* Wq  = (const float*)d_in[4];
    const float* bq  = (const float*)d_in[5];
    const float* Wk  = (const float*)d_in[6];
    const float* bk  = (const float*)d_in[7];
    float* out = (float*)d_out;

    void *p_part, *p_k, *p_fbq;
    cudaGetSymbolAddress(&p_part, g_part);
    cudaGetSymbolAddress(&p_k,    g_k);
    cudaGetSymbolAddress(&p_fbq,  g_fbq);

    // 1) k partials: f_w[80,512] @ Wk^T        (NT, K-split 4)
    gemm_part<true><<<dim3(5, 4, 4), 128>>>(f_w, Wk, (float*)p_part,
                                            KR, D_, D_, D_, 4, 0, 0);
    // 2) k = sum + bk ; c = bq . k
    reduce_k_bias<<<KR, 512>>>(bk, bq);
    // 3) kk partials: k @ Wq                   (NN, K-split 4)
    gemm_part<false><<<dim3(5, 4, 4), 128>>>((const float*)p_k, Wq, (float*)p_part,
                                             KR, D_, D_, D_, 4, 0, 0);
    reduce_kk<<<40, 256>>>();
    // 4) cross-attn softmax + gating -> f_bq
    attn_kernel<<<B_*N_, 256>>>(f_b, f_w, f_s);
    // 5) self-attn score partials per batch    (NT, batched, K-split 4)
    gemm_part<true><<<dim3(8, 1, 16), 128>>>((const float*)p_fbq, (const float*)p_fbq,
                                             (float*)p_part, N_, N_, D_, D_, 4,
                                             N_*D_, N_*D_);
    score_softmax<<<B_*N_, 128>>>();
    // 6) DRAM-bound f_m stream, m-split x4 for occupancy
    final_split<<<512, 512>>>(f_b, f_s, f_m);
    reduce_final<<<128, 512>>>(f_b, out);
}